// round 7
// baseline (speedup 1.0000x reference)
#include <cuda_runtime.h>
#include <cuda_fp16.h>

#define BB 4
#define CC 64
#define FD 50000
#define KN 16
#define BN_EPS 1e-5f

// Scratch: transformed features g[b][f][o] in fp16 (face-major, 128B rows)
__device__ __half g_buf[BB * FD * CC];
__device__ float g_sum[CC];
__device__ float g_sq[CC];

// ---------------------------------------------------------------------------
// Packed f32x2 helpers (Blackwell FFMA2 path — ptxas won't auto-fuse this)
__device__ __forceinline__ unsigned long long pk2(float x, float y) {
    unsigned long long r;
    asm("mov.b64 %0, {%1, %2};" : "=l"(r) : "f"(x), "f"(y));
    return r;
}
__device__ __forceinline__ void upk2(unsigned long long v, float& x, float& y) {
    asm("mov.b64 {%0, %1}, %2;" : "=f"(x), "=f"(y) : "l"(v));
}
__device__ __forceinline__ void fma2(unsigned long long& d,
                                     unsigned long long a,
                                     unsigned long long b) {
    asm("fma.rn.f32x2 %0, %1, %2, %0;" : "+l"(d) : "l"(a), "l"(b));
}

// ---------------------------------------------------------------------------
// GEMM: g[b][f][o] = sum_c W[o][c] * fea[b][c][f], fp16 output.
// Staged smem; microtile 4 faces x 16 outputs per thread (high face reuse:
// 8 wf per 32 warp-FFMA2). Block: 128 threads = 4 warps; warp ty owns outputs
// 16ty..16ty+15 across all 128 faces of the tile.
__global__ __launch_bounds__(128) void gemm_kernel(const float* __restrict__ fea,
                                                   const float* __restrict__ W) {
    __shared__ float  sF[64][128];    // [c][f]          32 KB
    __shared__ float4 sW4[64][16];    // [c][o/4] quads  16 KB
    const int b = blockIdx.y;
    const int f0 = blockIdx.x * 128;
    const int t = threadIdx.x;
    const int warp = t >> 5, lane = t & 31;

    // fold stats zeroing into this kernel (runs before gather)
    if (f0 == 0 && b == 0 && t < CC) { g_sum[t] = 0.f; g_sq[t] = 0.f; }

    // Stage fea tile: warp per c-row, float4 lanes. Valid span is 4-aligned.
    const float* feab = fea + (size_t)b * (CC * FD);
    const int nv = min(128, FD - f0);
    for (int c = warp; c < 64; c += 4) {
        const float* src = feab + c * FD + f0;
        float4 v = make_float4(0.f, 0.f, 0.f, 0.f);
        if (4 * lane + 3 < nv) v = *(const float4*)(src + 4 * lane);
        ((float4*)&sF[c][0])[lane] = v;
    }
    // sW4[c][j] = (W[4j][c], W[4j+1][c], W[4j+2][c], W[4j+3][c])
    for (int i = t; i < 64 * 16; i += 128) {
        int c = i >> 4, j = i & 15;
        sW4[c][j] = make_float4(W[(4 * j) * CC + c], W[(4 * j + 1) * CC + c],
                                W[(4 * j + 2) * CC + c], W[(4 * j + 3) * CC + c]);
    }
    __syncthreads();

    const int tx = t & 31;   // face quad: faces 4tx .. 4tx+3
    const int ty = t >> 5;   // output group: outputs ty*16 .. ty*16+15

    unsigned long long acc2[4][8];   // [face][output pair]
#pragma unroll
    for (int i = 0; i < 4; i++)
#pragma unroll
        for (int j = 0; j < 8; j++) acc2[i][j] = 0ull;

#pragma unroll 2
    for (int c = 0; c < 64; c++) {
        float4 a = ((const float4*)&sF[c][0])[tx];                 // LDS.128
        // 16 outputs = 8 f32x2 pairs = 4 broadcast LDS.128
        ulonglong2 w0 = ((const ulonglong2*)&sW4[c][0])[4 * ty];
        ulonglong2 w1 = ((const ulonglong2*)&sW4[c][0])[4 * ty + 1];
        ulonglong2 w2 = ((const ulonglong2*)&sW4[c][0])[4 * ty + 2];
        ulonglong2 w3 = ((const ulonglong2*)&sW4[c][0])[4 * ty + 3];
        unsigned long long pa0 = pk2(a.x, a.x);
        unsigned long long pa1 = pk2(a.y, a.y);
        unsigned long long pa2 = pk2(a.z, a.z);
        unsigned long long pa3 = pk2(a.w, a.w);
#pragma unroll
        for (int i = 0; i < 4; i++) {
            unsigned long long pa = (i == 0) ? pa0 : (i == 1) ? pa1 : (i == 2) ? pa2 : pa3;
            fma2(acc2[i][0], pa, w0.x); fma2(acc2[i][1], pa, w0.y);
            fma2(acc2[i][2], pa, w1.x); fma2(acc2[i][3], pa, w1.y);
            fma2(acc2[i][4], pa, w2.x); fma2(acc2[i][5], pa, w2.y);
            fma2(acc2[i][6], pa, w3.x); fma2(acc2[i][7], pa, w3.y);
        }
    }

    __half* gb = g_buf + (size_t)b * (FD * CC);
#pragma unroll
    for (int i = 0; i < 4; i++) {
        int fg = f0 + 4 * tx + i;
        if (fg < FD) {
            union { __half2 h[8]; uint4 u[2]; } pk;
#pragma unroll
            for (int jj = 0; jj < 8; jj++) {
                float lo, hi;
                upk2(acc2[i][jj], lo, hi);
                pk.h[jj] = __floats2half2_rn(lo, hi);
            }
            uint4* dst = (uint4*)(gb + (size_t)fg * CC + ty * 16);
            dst[0] = pk.u[0];
            dst[1] = pk.u[1];
        }
    }
}

// ---------------------------------------------------------------------------
// Gather + bias + stats, writes y into d_out in [B, C, F] layout.
// Warp per 4 faces; lane owns channels (2*lane, 2*lane+1) -> one half2 LDG.32
// per neighbor row (warp covers the full 128B row). fp32 accumulation.
__global__ __launch_bounds__(256) void gather_kernel(const int* __restrict__ ring,
                                                     const float* __restrict__ bias,
                                                     float* __restrict__ out) {
    __shared__ float tile[32][65];      // [f_local][c], padded
    __shared__ float s_sum[CC];
    __shared__ float s_sq[CC];

    const int t = threadIdx.x;
    if (t < CC) { s_sum[t] = 0.f; s_sq[t] = 0.f; }
    __syncthreads();

    const int b = blockIdx.y;
    const int f0 = blockIdx.x * 32;
    const int warp = t >> 5, lane = t & 31;
    const __half2* gb = (const __half2*)(g_buf + (size_t)b * (FD * CC));
    const float bias0 = bias[2 * lane];
    const float bias1 = bias[2 * lane + 1];

    float s0 = 0.f, s1 = 0.f, q0 = 0.f, q1 = 0.f;

#pragma unroll
    for (int i = 0; i < 4; i++) {
        int f = f0 + warp * 4 + i;              // warp-uniform
        if (f >= FD) continue;
        const int* rp = ring + ((long long)(b * FD + f)) * KN;
        int myidx = (lane < KN) ? rp[lane] : 0;
        if ((unsigned)myidx >= (unsigned)FD) myidx = 0;   // defensive
        float accx = 0.f, accy = 0.f;
#pragma unroll
        for (int k = 0; k < KN; k++) {
            int idx = __shfl_sync(0xffffffffu, myidx, k);
            float2 v = __half22float2(gb[(size_t)idx * 32 + lane]);
            accx += v.x;
            accy += v.y;
        }
        float y0 = accx + bias0;
        float y1 = accy + bias1;
        tile[warp * 4 + i][2 * lane]     = y0;
        tile[warp * 4 + i][2 * lane + 1] = y1;
        s0 += y0; q0 += y0 * y0;
        s1 += y1; q1 += y1 * y1;
    }

    atomicAdd(&s_sum[2 * lane],     s0);
    atomicAdd(&s_sum[2 * lane + 1], s1);
    atomicAdd(&s_sq[2 * lane],      q0);
    atomicAdd(&s_sq[2 * lane + 1],  q1);
    __syncthreads();

    // Transposed, coalesced write: out[b][c][f0+lane]
    const int nf = min(32, FD - f0);
    for (int c = warp; c < CC; c += 8) {
        if (lane < nf)
            out[((size_t)b * CC + c) * FD + f0 + lane] = tile[lane][c];
    }

    if (t < CC) {
        atomicAdd(&g_sum[t], s_sum[t]);
        atomicAdd(&g_sq[t],  s_sq[t]);
    }
}

// ---------------------------------------------------------------------------
// In-place normalize + ReLU over d_out, float4 vectorized, BN finalize inline.
// 3,200,000 float4 = 12500 blocks x 256 threads exactly.
__global__ __launch_bounds__(256) void norm_kernel(const float* __restrict__ gamma,
                                                   const float* __restrict__ beta,
                                                   float* __restrict__ out) {
    int i = blockIdx.x * 256 + threadIdx.x;       // float4 index
    int c = (i / (FD / 4)) & 63;                  // channel
    const float inv_n = 1.0f / (float)(BB * FD);
    float mean = g_sum[c] * inv_n;
    float var  = g_sq[c] * inv_n - mean * mean;
    float sc = gamma[c] * rsqrtf(var + BN_EPS);
    float sh = beta[c] - mean * sc;
    float4 v = ((float4*)out)[i];
    v.x = fmaxf(fmaf(v.x, sc, sh), 0.f);
    v.y = fmaxf(fmaf(v.y, sc, sh), 0.f);
    v.z = fmaxf(fmaf(v.z, sc, sh), 0.f);
    v.w = fmaxf(fmaf(v.w, sc, sh), 0.f);
    ((float4*)out)[i] = v;
}

// ---------------------------------------------------------------------------
extern "C" void kernel_launch(void* const* d_in, const int* in_sizes, int n_in,
                              void* d_out, int out_size) {
    const float* fea   = (const float*)d_in[0];      // [B, C_in, F]
    const int*   ring  = (const int*)d_in[1];        // [B, F, K] int32
    const float* W     = (const float*)d_in[2];      // [C_out, C_in]
    const float* bias  = (const float*)d_in[3];      // [C_out]
    const float* gamma = (const float*)d_in[4];      // [C_out]
    const float* beta  = (const float*)d_in[5];      // [C_out]
    float*       out   = (float*)d_out;              // [B, C_out, F]

    dim3 gg((FD + 127) / 128, BB);
    gemm_kernel<<<gg, 128>>>(fea, W);

    dim3 gt((FD + 31) / 32, BB);
    gather_kernel<<<gt, 256>>>(ring, bias, out);

    norm_kernel<<<(BB * CC * FD / 4) / 256, 256>>>(gamma, beta, out);
}

// round 9
// speedup vs baseline: 1.2604x; 1.2604x over previous
#include <cuda_runtime.h>
#include <cuda_fp16.h>
#include <cstdint>

#define BB 4
#define CC 64
#define FD 50000
#define KN 16
#define BN_EPS 1e-5f

// Scratch: transformed features g[b][f][o] in fp16 (face-major, 128B rows)
__device__ __half g_buf[BB * FD * CC];
__device__ float g_sum[CC];
__device__ float g_sq[CC];

// ---------------------------------------------------------------------------
__device__ __forceinline__ uint32_t smem_u32(const void* p) {
    uint32_t a;
    asm("{ .reg .u64 t; cvta.to.shared.u64 t, %1; cvt.u32.u64 %0, t; }"
        : "=r"(a) : "l"(p));
    return a;
}

__device__ __forceinline__ void ldsm_x4(uint32_t& r0, uint32_t& r1,
                                        uint32_t& r2, uint32_t& r3, uint32_t addr) {
    asm volatile("ldmatrix.sync.aligned.m8n8.x4.shared.b16 {%0,%1,%2,%3}, [%4];"
                 : "=r"(r0), "=r"(r1), "=r"(r2), "=r"(r3) : "r"(addr));
}

__device__ __forceinline__ void mma16816(float* c, uint32_t a0, uint32_t a1,
                                         uint32_t a2, uint32_t a3,
                                         uint32_t b0, uint32_t b1) {
    asm volatile(
        "mma.sync.aligned.m16n8k16.row.col.f32.f16.f16.f32 "
        "{%0,%1,%2,%3}, {%4,%5,%6,%7}, {%8,%9}, {%0,%1,%2,%3};"
        : "+f"(c[0]), "+f"(c[1]), "+f"(c[2]), "+f"(c[3])
        : "r"(a0), "r"(a1), "r"(a2), "r"(a3), "r"(b0), "r"(b1));
}

// ---------------------------------------------------------------------------
// GEMM via mma.sync: per CTA D[128f][64o] = A[128f][64c] * B[64o][64c]^T
// A = fea^T tile fp16 (staged smem transpose), B = W fp16, fp32 accum.
// Block 256 = 8 warps; warp w owns faces w*16..w*16+15, all 64 outputs.
#define SPA 72   // padded row stride (halves): 144B -> LDSM rows on distinct banks
__global__ __launch_bounds__(256)
void gemm_kernel(const float* __restrict__ fea, const float* __restrict__ W) {
    __shared__ float sStage[64][68];               // fp32 [c][f-half] stage
    __shared__ __align__(16) __half sA[128 * SPA]; // [f][c] padded
    __shared__ __align__(16) __half sB[64 * SPA];  // [o][c] padded

    const int b = blockIdx.y;
    const int f0 = blockIdx.x * 128;
    const int t = threadIdx.x;
    const int wid = t >> 5, lane = t & 31;

    // fold stats zeroing into this kernel (runs before gather)
    if (f0 == 0 && b == 0 && t < CC) { g_sum[t] = 0.f; g_sq[t] = 0.f; }

    // ---- stage B = W [64o][64c] -> fp16 padded rows ----
    {
        const int o = t >> 2, q = t & 3;           // 64 rows x 4 quarters
        union { __half2 h2[8]; uint4 u[2]; } pk;
#pragma unroll
        for (int i = 0; i < 4; i++) {
            float4 wv = *(const float4*)(W + o * CC + q * 16 + 4 * i);
            pk.h2[2 * i]     = __floats2half2_rn(wv.x, wv.y);
            pk.h2[2 * i + 1] = __floats2half2_rn(wv.z, wv.w);
        }
        uint4* dst = (uint4*)(sB + o * SPA + q * 16);
        dst[0] = pk.u[0];
        dst[1] = pk.u[1];
    }

    // ---- stage A = fea^T tile [128f][64c] fp16, two 64-face passes ----
    const float* feab = fea + (size_t)b * (CC * FD);
#pragma unroll
    for (int h = 0; h < 2; h++) {
        const int fh0 = f0 + 64 * h;
        const int nvh = min(64, FD - fh0);         // may be <=0 -> zero pad
        __syncthreads();
        for (int i = t; i < 64 * 16; i += 256) {   // coalesced fp32 loads
            int c = i >> 4, q = i & 15;
            float4 v = make_float4(0.f, 0.f, 0.f, 0.f);
            if (4 * q + 3 < nvh) v = *(const float4*)(feab + c * FD + fh0 + 4 * q);
            *(float4*)&sStage[c][4 * q] = v;
        }
        __syncthreads();
        {   // transpose: thread owns face fl, 16 channels
            const int fl = t & 63;
            const int ch = (t >> 6) * 16;
            float v[16];
#pragma unroll
            for (int j = 0; j < 16; j++) v[j] = sStage[ch + j][fl];  // lane=col: conflict-free
            union { __half2 h2[8]; uint4 u[2]; } pk;
#pragma unroll
            for (int m = 0; m < 8; m++)
                pk.h2[m] = __floats2half2_rn(v[2 * m], v[2 * m + 1]);
            uint4* dst = (uint4*)(sA + (64 * h + fl) * SPA + ch);
            dst[0] = pk.u[0];
            dst[1] = pk.u[1];
        }
    }
    __syncthreads();

    // ---- MMA mainloop: 4 K-steps x 8 n-tiles per warp ----
    const uint32_t aBase = smem_u32(sA);
    const uint32_t bBase = smem_u32(sB);
    // A lane addressing: row = w*16 + ((l>>3)&1)*8 + (l&7), col = kk*16 + (l>>4)*8
    const uint32_t aRow = wid * 16 + ((lane >> 3) & 1) * 8 + (lane & 7);
    const uint32_t aColOff = (lane >> 4) * 8;
    // B lane addressing: row = 16j + (l>>4)*8 + (l&7), col = kk*16 + ((l>>3)&1)*8
    const uint32_t bRowOff = (lane >> 4) * 8 + (lane & 7);
    const uint32_t bColOff = ((lane >> 3) & 1) * 8;

    float acc[8][4];
#pragma unroll
    for (int j = 0; j < 8; j++)
#pragma unroll
        for (int m = 0; m < 4; m++) acc[j][m] = 0.f;

#pragma unroll
    for (int kk = 0; kk < 4; kk++) {
        uint32_t a0, a1, a2, a3;
        ldsm_x4(a0, a1, a2, a3,
                aBase + (aRow * SPA + kk * 16 + aColOff) * 2);
#pragma unroll
        for (int j = 0; j < 4; j++) {              // two n-tiles per ldmatrix.x4
            uint32_t b0, b1, b2, b3;
            ldsm_x4(b0, b1, b2, b3,
                    bBase + ((16 * j + bRowOff) * SPA + kk * 16 + bColOff) * 2);
            mma16816(acc[2 * j],     a0, a1, a2, a3, b0, b1);
            mma16816(acc[2 * j + 1], a0, a1, a2, a3, b2, b3);
        }
    }

    // ---- epilogue: C frag -> g_buf[f][o] fp16 (half2 stores) ----
    const int fr = f0 + wid * 16 + (lane >> 2);
    const int colq = 2 * (lane & 3);
    __half* gb = g_buf + (size_t)b * (FD * CC);
    if (fr < FD) {
        __half* row = gb + (size_t)fr * CC;
#pragma unroll
        for (int j = 0; j < 8; j++)
            *(__half2*)(row + 8 * j + colq) = __floats2half2_rn(acc[j][0], acc[j][1]);
    }
    if (fr + 8 < FD) {
        __half* row = gb + (size_t)(fr + 8) * CC;
#pragma unroll
        for (int j = 0; j < 8; j++)
            *(__half2*)(row + 8 * j + colq) = __floats2half2_rn(acc[j][2], acc[j][3]);
    }
}

// ---------------------------------------------------------------------------
// Gather + bias + stats, writes y into d_out in [B, C, F] layout.
// Warp per 4 faces; lane owns channels (2*lane, 2*lane+1) -> one half2 LDG.32
// per neighbor row (warp covers the full 128B row). fp32 accumulation.
__global__ __launch_bounds__(256) void gather_kernel(const int* __restrict__ ring,
                                                     const float* __restrict__ bias,
                                                     float* __restrict__ out) {
    __shared__ float tile[32][65];      // [f_local][c], padded
    __shared__ float s_sum[CC];
    __shared__ float s_sq[CC];

    const int t = threadIdx.x;
    if (t < CC) { s_sum[t] = 0.f; s_sq[t] = 0.f; }
    __syncthreads();

    const int b = blockIdx.y;
    const int f0 = blockIdx.x * 32;
    const int warp = t >> 5, lane = t & 31;
    const __half2* gb = (const __half2*)(g_buf + (size_t)b * (FD * CC));
    const float bias0 = bias[2 * lane];
    const float bias1 = bias[2 * lane + 1];

    float s0 = 0.f, s1 = 0.f, q0 = 0.f, q1 = 0.f;

#pragma unroll
    for (int i = 0; i < 4; i++) {
        int f = f0 + warp * 4 + i;              // warp-uniform
        if (f >= FD) continue;
        const int* rp = ring + ((long long)(b * FD + f)) * KN;
        int myidx = (lane < KN) ? rp[lane] : 0;
        if ((unsigned)myidx >= (unsigned)FD) myidx = 0;   // defensive
        float accx = 0.f, accy = 0.f;
#pragma unroll
        for (int k = 0; k < KN; k++) {
            int idx = __shfl_sync(0xffffffffu, myidx, k);
            float2 v = __half22float2(gb[(size_t)idx * 32 + lane]);
            accx += v.x;
            accy += v.y;
        }
        float y0 = accx + bias0;
        float y1 = accy + bias1;
        tile[warp * 4 + i][2 * lane]     = y0;
        tile[warp * 4 + i][2 * lane + 1] = y1;
        s0 += y0; q0 += y0 * y0;
        s1 += y1; q1 += y1 * y1;
    }

    atomicAdd(&s_sum[2 * lane],     s0);
    atomicAdd(&s_sum[2 * lane + 1], s1);
    atomicAdd(&s_sq[2 * lane],      q0);
    atomicAdd(&s_sq[2 * lane + 1],  q1);
    __syncthreads();

    // Transposed, coalesced write: out[b][c][f0+lane]
    const int nf = min(32, FD - f0);
    for (int c = warp; c < CC; c += 8) {
        if (lane < nf)
            out[((size_t)b * CC + c) * FD + f0 + lane] = tile[lane][c];
    }

    if (t < CC) {
        atomicAdd(&g_sum[t], s_sum[t]);
        atomicAdd(&g_sq[t],  s_sq[t]);
    }
}

// ---------------------------------------------------------------------------
// In-place normalize + ReLU over d_out, float4 vectorized, BN finalize inline.
// 3,200,000 float4 = 12500 blocks x 256 threads exactly.
__global__ __launch_bounds__(256) void norm_kernel(const float* __restrict__ gamma,
                                                   const float* __restrict__ beta,
                                                   float* __restrict__ out) {
    int i = blockIdx.x * 256 + threadIdx.x;       // float4 index
    int c = (i / (FD / 4)) & 63;                  // channel
    const float inv_n = 1.0f / (float)(BB * FD);
    float mean = g_sum[c] * inv_n;
    float var  = g_sq[c] * inv_n - mean * mean;
    float sc = gamma[c] * rsqrtf(var + BN_EPS);
    float sh = beta[c] - mean * sc;
    float4 v = ((float4*)out)[i];
    v.x = fmaxf(fmaf(v.x, sc, sh), 0.f);
    v.y = fmaxf(fmaf(v.y, sc, sh), 0.f);
    v.z = fmaxf(fmaf(v.z, sc, sh), 0.f);
    v.w = fmaxf(fmaf(v.w, sc, sh), 0.f);
    ((float4*)out)[i] = v;
}

// ---------------------------------------------------------------------------
extern "C" void kernel_launch(void* const* d_in, const int* in_sizes, int n_in,
                              void* d_out, int out_size) {
    const float* fea   = (const float*)d_in[0];      // [B, C_in, F]
    const int*   ring  = (const int*)d_in[1];        // [B, F, K] int32
    const float* W     = (const float*)d_in[2];      // [C_out, C_in]
    const float* bias  = (const float*)d_in[3];      // [C_out]
    const float* gamma = (const float*)d_in[4];      // [C_out]
    const float* beta  = (const float*)d_in[5];      // [C_out]
    float*       out   = (float*)d_out;              // [B, C_out, F]

    dim3 gg((FD + 127) / 128, BB);
    gemm_kernel<<<gg, 256>>>(fea, W);

    dim3 gt((FD + 31) / 32, BB);
    gather_kernel<<<gt, 256>>>(ring, bias, out);

    norm_kernel<<<(BB * CC * FD / 4) / 256, 256>>>(gamma, beta, out);
}

// round 10
// speedup vs baseline: 1.3452x; 1.0672x over previous
#include <cuda_runtime.h>
#include <cuda_fp16.h>
#include <cstdint>

#define BB 4
#define CC 64
#define FD 50000
#define KN 16
#define BN_EPS 1e-5f

// Scratch: transformed features g[b][f][o] in fp16 (face-major, 128B rows)
__device__ __half g_buf[BB * FD * CC];
__device__ float g_sum[CC];
__device__ float g_sq[CC];

// ---------------------------------------------------------------------------
__device__ __forceinline__ uint32_t smem_u32(const void* p) {
    uint32_t a;
    asm("{ .reg .u64 t; cvta.to.shared.u64 t, %1; cvt.u32.u64 %0, t; }"
        : "=r"(a) : "l"(p));
    return a;
}

__device__ __forceinline__ void ldsm_x4(uint32_t& r0, uint32_t& r1,
                                        uint32_t& r2, uint32_t& r3, uint32_t addr) {
    asm volatile("ldmatrix.sync.aligned.m8n8.x4.shared.b16 {%0,%1,%2,%3}, [%4];"
                 : "=r"(r0), "=r"(r1), "=r"(r2), "=r"(r3) : "r"(addr));
}

__device__ __forceinline__ void ldsm_x4_trans(uint32_t& r0, uint32_t& r1,
                                              uint32_t& r2, uint32_t& r3, uint32_t addr) {
    asm volatile("ldmatrix.sync.aligned.m8n8.x4.trans.shared.b16 {%0,%1,%2,%3}, [%4];"
                 : "=r"(r0), "=r"(r1), "=r"(r2), "=r"(r3) : "r"(addr));
}

__device__ __forceinline__ void mma16816(float* c, uint32_t a0, uint32_t a1,
                                         uint32_t a2, uint32_t a3,
                                         uint32_t b0, uint32_t b1) {
    asm volatile(
        "mma.sync.aligned.m16n8k16.row.col.f32.f16.f16.f32 "
        "{%0,%1,%2,%3}, {%4,%5,%6,%7}, {%8,%9}, {%0,%1,%2,%3};"
        : "+f"(c[0]), "+f"(c[1]), "+f"(c[2]), "+f"(c[3])
        : "r"(a0), "r"(a1), "r"(a2), "r"(a3), "r"(b0), "r"(b1));
}

// ---------------------------------------------------------------------------
// GEMM via mma.sync: per CTA D[128f][64o] = A[128f][64c] * B[64o][64c]^T
// A stored as-is in [c][f] fp16 rows (NO transpose pass); A-frags loaded via
// ldmatrix.x4.trans. B = W fp16 [o][c]. fp32 accum.
// Block 256 = 8 warps; warp w owns faces w*16..w*16+15, all 64 outputs.
#define SPA 136  // sA row stride in halves: 272B == 16 mod 128 -> LDSM rows on distinct banks
#define SPB 72   // sB row stride in halves: 144B == 16 mod 128
__global__ __launch_bounds__(256)
void gemm_kernel(const float* __restrict__ fea, const float* __restrict__ W) {
    __shared__ __align__(16) __half sA[64 * SPA];  // [c][f]  17 KB
    __shared__ __align__(16) __half sB[64 * SPB];  // [o][c]   9 KB

    const int b = blockIdx.y;
    const int f0 = blockIdx.x * 128;
    const int t = threadIdx.x;
    const int wid = t >> 5, lane = t & 31;

    // fold stats zeroing into this kernel (runs before gather)
    if (f0 == 0 && b == 0 && t < CC) { g_sum[t] = 0.f; g_sq[t] = 0.f; }

    // ---- stage B = W [64o][64c] -> fp16 padded rows ----
    {
        const int o = t >> 2, q = t & 3;           // 64 rows x 4 quarters
        union { __half2 h2[8]; uint4 u[2]; } pk;
#pragma unroll
        for (int i = 0; i < 4; i++) {
            float4 wv = *(const float4*)(W + o * CC + q * 16 + 4 * i);
            pk.h2[2 * i]     = __floats2half2_rn(wv.x, wv.y);
            pk.h2[2 * i + 1] = __floats2half2_rn(wv.z, wv.w);
        }
        uint4* dst = (uint4*)(sB + o * SPB + q * 16);
        dst[0] = pk.u[0];
        dst[1] = pk.u[1];
    }

    // ---- stage A = fea tile [64c][128f] fp16, stored as-is (no transpose) ----
    const float* feab = fea + (size_t)b * (CC * FD);
    const int nv = min(128, FD - f0);              // valid span, 4-aligned
    {
        const int c = t >> 2, q = t & 3;           // 4 threads per c-row
        const float* src = feab + c * FD + f0 + q * 32;
        __half* dstrow = sA + c * SPA + q * 32;
#pragma unroll
        for (int i = 0; i < 8; i++) {
            float4 v = make_float4(0.f, 0.f, 0.f, 0.f);
            if (q * 32 + 4 * i + 3 < nv) v = *(const float4*)(src + 4 * i);
            union { __half2 h2[2]; unsigned long long u; } pk;
            pk.h2[0] = __floats2half2_rn(v.x, v.y);
            pk.h2[1] = __floats2half2_rn(v.z, v.w);
            *(unsigned long long*)(dstrow + 4 * i) = pk.u;
        }
    }
    __syncthreads();

    // ---- MMA mainloop: 4 K-steps x 8 n-tiles per warp ----
    const uint32_t aBase = smem_u32(sA);
    const uint32_t bBase = smem_u32(sB);
    const int m0 = wid * 16;
    // A-frag via trans: group g = lane>>3, r = lane&7
    //   matrix0: k rows kk*16+r,     m col m0      -> a0 (m0:8,  k0:8)
    //   matrix1: k rows kk*16+r,     m col m0+8    -> a1 (m8:16, k0:8)
    //   matrix2: k rows kk*16+8+r,   m col m0      -> a2 (m0:8,  k8:16)
    //   matrix3: k rows kk*16+8+r,   m col m0+8    -> a3 (m8:16, k8:16)
    const int g = lane >> 3, r = lane & 7;
    const uint32_t aKoff = (g >> 1) * 8 + r;       // within-K-step row
    const uint32_t aMcol = m0 + (g & 1) * 8;
    // B lane addressing (non-trans, unchanged from R9)
    const uint32_t bRowOff = (lane >> 4) * 8 + (lane & 7);
    const uint32_t bColOff = ((lane >> 3) & 1) * 8;

    float acc[8][4];
#pragma unroll
    for (int j = 0; j < 8; j++)
#pragma unroll
        for (int m = 0; m < 4; m++) acc[j][m] = 0.f;

#pragma unroll
    for (int kk = 0; kk < 4; kk++) {
        uint32_t a0, a1, a2, a3;
        ldsm_x4_trans(a0, a1, a2, a3,
                      aBase + ((kk * 16 + aKoff) * SPA + aMcol) * 2);
#pragma unroll
        for (int j = 0; j < 4; j++) {              // two n-tiles per ldmatrix.x4
            uint32_t b0, b1, b2, b3;
            ldsm_x4(b0, b1, b2, b3,
                    bBase + ((16 * j + bRowOff) * SPB + kk * 16 + bColOff) * 2);
            mma16816(acc[2 * j],     a0, a1, a2, a3, b0, b1);
            mma16816(acc[2 * j + 1], a0, a1, a2, a3, b2, b3);
        }
    }

    // ---- epilogue: C frag -> g_buf[f][o] fp16 (half2 stores) ----
    const int fr = f0 + m0 + (lane >> 2);
    const int colq = 2 * (lane & 3);
    __half* gb = g_buf + (size_t)b * (FD * CC);
    if (fr < FD) {
        __half* row = gb + (size_t)fr * CC;
#pragma unroll
        for (int j = 0; j < 8; j++)
            *(__half2*)(row + 8 * j + colq) = __floats2half2_rn(acc[j][0], acc[j][1]);
    }
    if (fr + 8 < FD) {
        __half* row = gb + (size_t)(fr + 8) * CC;
#pragma unroll
        for (int j = 0; j < 8; j++)
            *(__half2*)(row + 8 * j + colq) = __floats2half2_rn(acc[j][2], acc[j][3]);
    }
}

// ---------------------------------------------------------------------------
// Gather + bias + stats, writes y into d_out in [B, C, F] layout.
// Warp per 4 faces; lane owns channels (2*lane, 2*lane+1) -> one half2 LDG.32
// per neighbor row (warp covers the full 128B row). fp32 accumulation.
__global__ __launch_bounds__(256) void gather_kernel(const int* __restrict__ ring,
                                                     const float* __restrict__ bias,
                                                     float* __restrict__ out) {
    __shared__ float tile[32][65];      // [f_local][c], padded
    __shared__ float s_sum[CC];
    __shared__ float s_sq[CC];

    const int t = threadIdx.x;
    if (t < CC) { s_sum[t] = 0.f; s_sq[t] = 0.f; }
    __syncthreads();

    const int b = blockIdx.y;
    const int f0 = blockIdx.x * 32;
    const int warp = t >> 5, lane = t & 31;
    const __half2* gb = (const __half2*)(g_buf + (size_t)b * (FD * CC));
    const float bias0 = bias[2 * lane];
    const float bias1 = bias[2 * lane + 1];

    float s0 = 0.f, s1 = 0.f, q0 = 0.f, q1 = 0.f;

#pragma unroll
    for (int i = 0; i < 4; i++) {
        int f = f0 + warp * 4 + i;              // warp-uniform
        if (f >= FD) continue;
        const int* rp = ring + ((long long)(b * FD + f)) * KN;
        int myidx = (lane < KN) ? rp[lane] : 0;
        if ((unsigned)myidx >= (unsigned)FD) myidx = 0;   // defensive
        float accx = 0.f, accy = 0.f;
#pragma unroll
        for (int k = 0; k < KN; k++) {
            int idx = __shfl_sync(0xffffffffu, myidx, k);
            float2 v = __half22float2(gb[(size_t)idx * 32 + lane]);
            accx += v.x;
            accy += v.y;
        }
        float y0 = accx + bias0;
        float y1 = accy + bias1;
        tile[warp * 4 + i][2 * lane]     = y0;
        tile[warp * 4 + i][2 * lane + 1] = y1;
        s0 += y0; q0 += y0 * y0;
        s1 += y1; q1 += y1 * y1;
    }

    atomicAdd(&s_sum[2 * lane],     s0);
    atomicAdd(&s_sum[2 * lane + 1], s1);
    atomicAdd(&s_sq[2 * lane],      q0);
    atomicAdd(&s_sq[2 * lane + 1],  q1);
    __syncthreads();

    // Transposed, coalesced write: out[b][c][f0+lane]
    const int nf = min(32, FD - f0);
    for (int c = warp; c < CC; c += 8) {
        if (lane < nf)
            out[((size_t)b * CC + c) * FD + f0 + lane] = tile[lane][c];
    }

    if (t < CC) {
        atomicAdd(&g_sum[t], s_sum[t]);
        atomicAdd(&g_sq[t],  s_sq[t]);
    }
}

// ---------------------------------------------------------------------------
// In-place normalize + ReLU over d_out, float4 vectorized, BN finalize inline.
// 3,200,000 float4 = 12500 blocks x 256 threads exactly.
__global__ __launch_bounds__(256) void norm_kernel(const float* __restrict__ gamma,
                                                   const float* __restrict__ beta,
                                                   float* __restrict__ out) {
    int i = blockIdx.x * 256 + threadIdx.x;       // float4 index
    int c = (i / (FD / 4)) & 63;                  // channel
    const float inv_n = 1.0f / (float)(BB * FD);
    float mean = g_sum[c] * inv_n;
    float var  = g_sq[c] * inv_n - mean * mean;
    float sc = gamma[c] * rsqrtf(var + BN_EPS);
    float sh = beta[c] - mean * sc;
    float4 v = ((float4*)out)[i];
    v.x = fmaxf(fmaf(v.x, sc, sh), 0.f);
    v.y = fmaxf(fmaf(v.y, sc, sh), 0.f);
    v.z = fmaxf(fmaf(v.z, sc, sh), 0.f);
    v.w = fmaxf(fmaf(v.w, sc, sh), 0.f);
    ((float4*)out)[i] = v;
}

// ---------------------------------------------------------------------------
extern "C" void kernel_launch(void* const* d_in, const int* in_sizes, int n_in,
                              void* d_out, int out_size) {
    const float* fea   = (const float*)d_in[0];      // [B, C_in, F]
    const int*   ring  = (const int*)d_in[1];        // [B, F, K] int32
    const float* W     = (const float*)d_in[2];      // [C_out, C_in]
    const float* bias  = (const float*)d_in[3];      // [C_out]
    const float* gamma = (const float*)d_in[4];      // [C_out]
    const float* beta  = (const float*)d_in[5];      // [C_out]
    float*       out   = (float*)d_out;              // [B, C_out, F]

    dim3 gg((FD + 127) / 128, BB);
    gemm_kernel<<<gg, 256>>>(fea, W);

    dim3 gt((FD + 31) / 32, BB);
    gather_kernel<<<gt, 256>>>(ring, bias, out);

    norm_kernel<<<(BB * CC * FD / 4) / 256, 256>>>(gamma, beta, out);
}